// round 12
// baseline (speedup 1.0000x reference)
#include <cuda_runtime.h>
#include <cuda_fp16.h>

#define NA   100000
#define NE   1200000
#define NC0  3125
#define ORIG 92
#define NBRF 41
#define AF   64
#define HF   128
#define COUT 128
#define KTOT 169
#define NKC  11       // 11*16 = 176 padded K
#define KPAD2 184     // smem A row stride in halves (368 B)
#define YRS   136     // smem Y staging row stride in halves (272 B = 17*16)
#define EPB  640      // edges per k_message block (NE/640 = 1875)
#define EPSF 1e-5f

// ---------------- device scratch (no allocation) ----------------
__device__ __align__(16) __half   g_xh[NA * AF];
__device__ __align__(16) float    g_x[NA * AF];
__device__ __align__(16) __half   g_y[(size_t)NE * COUT];
__device__ __align__(16) __half   g_nbrh[(size_t)NE * 48];
__device__ __align__(16) float    g_accum[NA * AF];
__device__ float    g_stats1[2 * COUT];
__device__ __align__(16) float    g_scale1[COUT];
__device__ __align__(16) float    g_shift1[COUT];
__device__ float    g_stats2[2 * AF];
__device__ __align__(16) float    g_scale2[AF];
__device__ __align__(16) float    g_shift2[AF];
__device__ __align__(16) unsigned g_wfrag[3 * NKC * 16 * 32 * 2];
__device__ float    g_pool[NC0 * AF];
__device__ float    g_cnt[NC0];

// fast math
__device__ __forceinline__ float fsp(float x) {
    return fmaxf(x, 0.f) + __logf(1.f + __expf(-fabsf(x)));
}
// sigmoid via tanh.approx: 1 MUFU instead of 2
__device__ __forceinline__ float fsig(float x) {
    float t;
    asm("tanh.approx.f32 %0, %1;" : "=f"(t) : "f"(0.5f * x));
    return fmaf(0.5f, t, 0.5f);
}

__device__ __forceinline__ void ldsm_x4(unsigned &r0, unsigned &r1,
                                        unsigned &r2, unsigned &r3,
                                        unsigned addr) {
    asm volatile("ldmatrix.sync.aligned.m8n8.x4.shared.b16 {%0,%1,%2,%3}, [%4];\n"
                 : "=r"(r0), "=r"(r1), "=r"(r2), "=r"(r3) : "r"(addr));
}
__device__ __forceinline__ void stsm_x4(unsigned addr, unsigned r0, unsigned r1,
                                        unsigned r2, unsigned r3) {
    asm volatile("stmatrix.sync.aligned.m8n8.x4.shared.b16 [%0], {%1,%2,%3,%4};\n"
                 :: "r"(addr), "r"(r0), "r"(r1), "r"(r2), "r"(r3));
}
__device__ __forceinline__ void cp16(unsigned sdst, const void* gsrc) {
    asm volatile("cp.async.cg.shared.global [%0], [%1], 16;\n"
                 :: "r"(sdst), "l"(gsrc));
}

// Y staging swizzle: 16B chunk index XOR low row bits (conflict-free copy-out)
__device__ __forceinline__ unsigned ybyte(int row, int chunk) {
    return (unsigned)(row * (YRS * 2) + ((chunk ^ (row & 7)) << 4));
}

// ---------------- nbr_fea pad+convert (+ global zero-init fused) ----------------
__global__ void k_nbrprep(const float* __restrict__ nbr) {
    size_t t = (size_t)blockIdx.x * blockDim.x + threadIdx.x;
    if (t < (size_t)NA * AF / 4)
        ((float4*)g_accum)[t] = make_float4(0.f, 0.f, 0.f, 0.f);
    if (blockIdx.x == 0) {
        if (threadIdx.x < 2 * COUT) g_stats1[threadIdx.x] = 0.f;
        if (threadIdx.x < 2 * AF)   g_stats2[threadIdx.x] = 0.f;
    }
    if (t >= (size_t)NE * 6) return;       // 6 chunks of 8 halves per edge
    int chunk = (int)(t % 6);
    size_t e = t / 6;
    int c0 = chunk * 8;
    __half h[8];
#pragma unroll
    for (int q = 0; q < 8; q++) {
        int c = c0 + q;
        h[q] = __float2half(c < NBRF ? nbr[e * NBRF + c] : 0.f);
    }
    *(uint4*)&g_nbrh[e * 48 + c0] = *(uint4*)h;
}

// ---------------- B-fragment prep ----------------
__global__ void k_wprep(const float* __restrict__ convW) {
    int i = blockIdx.x * blockDim.x + threadIdx.x;
    int total = 3 * NKC * 16 * 32;
    if (i >= total) return;
    int lane = i & 31;
    int t = i >> 5;
    int nn = t & 15; t >>= 4;
    int kk = t % NKC;
    int l  = t / NKC;
    int n  = nn * 8 + (lane >> 2);
    int kbase = kk * 16 + (lane & 3) * 2;
#pragma unroll
    for (int rgp = 0; rgp < 2; rgp++) {
        int k = kbase + rgp * 8;
        float v0 = (k     < KTOT) ? convW[((size_t)l * KTOT + k)     * COUT + n] : 0.f;
        float v1 = (k + 1 < KTOT) ? convW[((size_t)l * KTOT + k + 1) * COUT + n] : 0.f;
        __half2 h = __floats2half2_rn(v0, v1);
        g_wfrag[(size_t)i * 2 + rgp] = *(unsigned*)&h;
    }
}

// ---------------- embedding ----------------
__global__ __launch_bounds__(256, 2)
void k_embed(const float* __restrict__ af, const float* __restrict__ W,
             const float* __restrict__ b) {
    __shared__ float sW[ORIG * AF];
    __shared__ float sAt[64 * 93];
    int tid = threadIdx.x;
    int a0  = blockIdx.x * 64;
    for (int i = tid; i < ORIG * AF; i += 256) sW[i] = W[i];
    for (int i = tid; i < 64 * ORIG; i += 256) {
        int rr = i / ORIG, kk = i % ORIG;
        int a = a0 + rr;
        sAt[rr * 93 + kk] = (a < NA) ? af[(size_t)a * ORIG + kk] : 0.f;
    }
    __syncthreads();
    int og = (tid & 15) * 4;
    int ag = (tid >> 4) * 4;
    float acc[4][4];
#pragma unroll
    for (int ii = 0; ii < 4; ii++)
#pragma unroll
        for (int j = 0; j < 4; j++) acc[ii][j] = 0.f;
    for (int k = 0; k < ORIG; k++) {
        float wv[4], av[4];
#pragma unroll
        for (int j = 0; j < 4; j++) wv[j] = sW[k * AF + og + j];
#pragma unroll
        for (int ii = 0; ii < 4; ii++) av[ii] = sAt[(ag + ii) * 93 + k];
#pragma unroll
        for (int ii = 0; ii < 4; ii++)
#pragma unroll
            for (int j = 0; j < 4; j++) acc[ii][j] += av[ii] * wv[j];
    }
#pragma unroll
    for (int ii = 0; ii < 4; ii++) {
        int a = a0 + ag + ii;
        if (a < NA) {
#pragma unroll
            for (int j = 0; j < 4; j++) {
                float v = acc[ii][j] + b[og + j];
                g_x[(size_t)a * AF + og + j]  = v;
                g_xh[(size_t)a * AF + og + j] = __float2half(v);
            }
        }
    }
}

// ---------------- edge GEMM + BN1 stats (R8 form) ----------------
__global__ __launch_bounds__(256, 2)
void k_edgegemm(const int* __restrict__ selfi,
                const int* __restrict__ nbri,
                int layer) {
    __shared__ __align__(16) __half sA[128][KPAD2];   // 47104 B (reused as sY)
    __shared__ float sSum[COUT];
    __shared__ float sSq[COUT];
    int tid = threadIdx.x;
    int e0  = blockIdx.x * 128;
    if (tid < COUT) { sSum[tid] = 0.f; sSq[tid] = 0.f; }

    unsigned abase = (unsigned)__cvta_generic_to_shared(&sA[0][0]);

    // gather [x_self | x_nbr | nbr] via cp.async: 2 threads per edge
    {
        int el = tid >> 1;
        int p  = tid & 1;
        int e  = e0 + el;
        int src = p ? nbri[e] : selfi[e];
        const uint4* xr = (const uint4*)(g_xh + (size_t)src * AF);
        unsigned drow = abase + (unsigned)(el * KPAD2 * 2);
        unsigned dx   = drow + (unsigned)(p * 128);
#pragma unroll
        for (int q = 0; q < 8; q++) cp16(dx + q * 16u, xr + q);
        const uint4* nr = (const uint4*)(g_nbrh + (size_t)e * 48);
        unsigned dn = drow + 256u + (unsigned)(p * 48);
#pragma unroll
        for (int q = 0; q < 3; q++) cp16(dn + q * 16u, nr + p * 3 + q);
    }
    asm volatile("cp.async.commit_group;\n");
    asm volatile("cp.async.wait_group 0;\n");
    __syncthreads();

    int lane = tid & 31;
    int warp = tid >> 5;
    int mrb = (warp & 3) * 32;
    int nh  = warp >> 2;
    int ncb = nh * 64;

    unsigned aaddr0 = abase + (unsigned)(((mrb + (lane & 15)) * KPAD2 + ((lane >> 4) * 8)) * 2);
    unsigned aaddr1 = aaddr0 + 16u * KPAD2 * 2u;

    const uint2* __restrict__ wf = (const uint2*)g_wfrag;
    size_t wbase = (((size_t)layer * NKC) * 16 + nh * 8) * 32 + lane;

    float acc[2][8][4];
#pragma unroll
    for (int mi = 0; mi < 2; mi++)
#pragma unroll
        for (int nn = 0; nn < 8; nn++)
#pragma unroll
            for (int r = 0; r < 4; r++) acc[mi][nn][r] = 0.f;

#pragma unroll
    for (int kk = 0; kk < NKC; kk++) {
        unsigned a[2][4];
        ldsm_x4(a[0][0], a[0][1], a[0][2], a[0][3], aaddr0 + kk * 32u);
        ldsm_x4(a[1][0], a[1][1], a[1][2], a[1][3], aaddr1 + kk * 32u);
        uint2 b[8];
#pragma unroll
        for (int nn = 0; nn < 8; nn++)
            b[nn] = wf[wbase + (size_t)kk * 16 * 32 + (size_t)nn * 32];
#pragma unroll
        for (int nn = 0; nn < 8; nn++) {
#pragma unroll
            for (int mi = 0; mi < 2; mi++) {
                asm volatile(
                    "mma.sync.aligned.m16n8k16.row.col.f32.f16.f16.f32 "
                    "{%0,%1,%2,%3}, {%4,%5,%6,%7}, {%8,%9}, {%0,%1,%2,%3};\n"
                    : "+f"(acc[mi][nn][0]), "+f"(acc[mi][nn][1]),
                      "+f"(acc[mi][nn][2]), "+f"(acc[mi][nn][3])
                    : "r"(a[mi][0]), "r"(a[mi][1]), "r"(a[mi][2]), "r"(a[mi][3]),
                      "r"(b[nn].x), "r"(b[nn].y));
            }
        }
    }

    // per-column sum/sumsq from registers
    float cs[8][2], cq[8][2];
#pragma unroll
    for (int nn = 0; nn < 8; nn++)
#pragma unroll
        for (int j = 0; j < 2; j++) { cs[nn][j] = 0.f; cq[nn][j] = 0.f; }
#pragma unroll
    for (int mi = 0; mi < 2; mi++)
#pragma unroll
        for (int nn = 0; nn < 8; nn++) {
            float d0 = acc[mi][nn][0], d1 = acc[mi][nn][1];
            float d2 = acc[mi][nn][2], d3 = acc[mi][nn][3];
            cs[nn][0] += d0 + d2; cq[nn][0] += d0 * d0 + d2 * d2;
            cs[nn][1] += d1 + d3; cq[nn][1] += d1 * d1 + d3 * d3;
        }
#pragma unroll
    for (int nn = 0; nn < 8; nn++)
#pragma unroll
        for (int j = 0; j < 2; j++) {
#pragma unroll
            for (int m = 4; m < 32; m <<= 1) {
                cs[nn][j] += __shfl_xor_sync(0xffffffffu, cs[nn][j], m);
                cq[nn][j] += __shfl_xor_sync(0xffffffffu, cq[nn][j], m);
            }
        }

    // stage y via stmatrix (reuse sA), then coalesced copy-out
    __syncthreads();
    {
        int tile = lane >> 3;
        int rrow = lane & 7;
        int rowb = mrb + ((tile & 1) ? 8 : 0) + rrow;
        int cchk = (ncb >> 3) + ((tile >> 1) ? 1 : 0);
#pragma unroll
        for (int mi = 0; mi < 2; mi++) {
            int row = rowb + mi * 16;
#pragma unroll
            for (int np = 0; np < 4; np++) {
                int nn = np * 2;
                __half2 h0  = __floats2half2_rn(acc[mi][nn][0],     acc[mi][nn][1]);
                __half2 h1  = __floats2half2_rn(acc[mi][nn][2],     acc[mi][nn][3]);
                __half2 h2v = __floats2half2_rn(acc[mi][nn + 1][0], acc[mi][nn + 1][1]);
                __half2 h3  = __floats2half2_rn(acc[mi][nn + 1][2], acc[mi][nn + 1][3]);
                stsm_x4(abase + ybyte(row, cchk + nn),
                        *(unsigned*)&h0, *(unsigned*)&h1,
                        *(unsigned*)&h2v, *(unsigned*)&h3);
            }
        }
    }
    __syncthreads();
    {
#pragma unroll
        for (int q = 0; q < 4; q++) {
            int idx = tid + q * 256;
            int row = idx >> 3;
            int j   = idx & 7;
            uint4 v0 = *(const uint4*)((const char*)&sA[0][0] + ybyte(row, 2 * j));
            *(uint4*)&g_y[(size_t)(e0 + row) * COUT + (2 * j) * 8] = v0;
            uint4 v1 = *(const uint4*)((const char*)&sA[0][0] + ybyte(row, 2 * j + 1));
            *(uint4*)&g_y[(size_t)(e0 + row) * COUT + (2 * j + 1) * 8] = v1;
        }
    }

    if (lane < 4) {
#pragma unroll
        for (int nn = 0; nn < 8; nn++)
#pragma unroll
            for (int j = 0; j < 2; j++) {
                int c = ncb + nn * 8 + lane * 2 + j;
                atomicAdd(&sSum[c], cs[nn][j]);
                atomicAdd(&sSq[c],  cq[nn][j]);
            }
    }
    __syncthreads();
    if (tid < COUT) {
        atomicAdd(&g_stats1[tid],        sSum[tid]);
        atomicAdd(&g_stats1[COUT + tid], sSq[tid]);
    }
}

// ---------------- BN1 prep (+ zero stats for next layer) ----------------
__global__ void k_bnprep1(const float* __restrict__ bn1g,
                          const float* __restrict__ bn1b, int layer) {
    int c = threadIdx.x;
    if (c < COUT) {
        float invE = 1.f / (float)NE;
        float m = g_stats1[c] * invE;
        float v = g_stats1[COUT + c] * invE - m * m;
        float sc = bn1g[layer * COUT + c] * rsqrtf(v + EPSF);
        g_scale1[c] = sc;
        g_shift1[c] = bn1b[layer * COUT + c] - m * sc;
        g_stats1[c] = 0.f;
        g_stats1[COUT + c] = 0.f;
    }
}

// ---------------- message + segment sum: 2 independent streams per thread ----------------
__global__ __launch_bounds__(256, 4)
void k_message(const int* __restrict__ selfi) {
    __shared__ int sIdx[EPB];
    int tid = threadIdx.x;
    int e0  = blockIdx.x * EPB;
    for (int i = tid; i < EPB; i += 256) sIdx[i] = selfi[e0 + i];
    __syncthreads();
    int c8 = tid & 7;          // 8-col group (filt c8*8.. / core 64+c8*8..)
    int j  = tid >> 3;         // 0..31 -> two 10-edge streams at 20j, 20j+10
    float scF[8], shF[8], scC[8], shC[8];
#pragma unroll
    for (int q = 0; q < 8; q++) {
        scF[q] = g_scale1[c8 * 8 + q];      shF[q] = g_shift1[c8 * 8 + q];
        scC[q] = g_scale1[64 + c8 * 8 + q]; shC[q] = g_shift1[64 + c8 * 8 + q];
    }
    int baseA = j * 20;
    int baseB = baseA + 10;
    float accA[8], accB[8];
#pragma unroll
    for (int q = 0; q < 8; q++) { accA[q] = 0.f; accB[q] = 0.f; }
    int curA = sIdx[baseA];
    int curB = sIdx[baseB];
#pragma unroll 2
    for (int t = 0; t < 10; t++) {
        size_t eA = (size_t)(e0 + baseA + t);
        size_t eB = (size_t)(e0 + baseB + t);
        uint4 fvA = *(const uint4*)&g_y[eA * COUT + c8 * 8];
        uint4 cvA = *(const uint4*)&g_y[eA * COUT + 64 + c8 * 8];
        uint4 fvB = *(const uint4*)&g_y[eB * COUT + c8 * 8];
        uint4 cvB = *(const uint4*)&g_y[eB * COUT + 64 + c8 * 8];
        int idxA = sIdx[baseA + t];
        int idxB = sIdx[baseB + t];
        if (idxA != curA) {
            float* dst = &g_accum[(size_t)curA * AF + c8 * 8];
#pragma unroll
            for (int q = 0; q < 8; q++) { atomicAdd(dst + q, accA[q]); accA[q] = 0.f; }
            curA = idxA;
        }
        if (idxB != curB) {
            float* dst = &g_accum[(size_t)curB * AF + c8 * 8];
#pragma unroll
            for (int q = 0; q < 8; q++) { atomicAdd(dst + q, accB[q]); accB[q] = 0.f; }
            curB = idxB;
        }
        const __half2* fhA = (const __half2*)&fvA;
        const __half2* chA = (const __half2*)&cvA;
        const __half2* fhB = (const __half2*)&fvB;
        const __half2* chB = (const __half2*)&cvB;
#pragma unroll
        for (int p = 0; p < 4; p++) {
            float2 fa = __half22float2(fhA[p]);
            float2 ca = __half22float2(chA[p]);
            float2 fb = __half22float2(fhB[p]);
            float2 cb = __half22float2(chB[p]);
            accA[2*p]   += fsig(fa.x * scF[2*p]   + shF[2*p])   * fsp(ca.x * scC[2*p]   + shC[2*p]);
            accA[2*p+1] += fsig(fa.y * scF[2*p+1] + shF[2*p+1]) * fsp(ca.y * scC[2*p+1] + shC[2*p+1]);
            accB[2*p]   += fsig(fb.x * scF[2*p]   + shF[2*p])   * fsp(cb.x * scC[2*p]   + shC[2*p]);
            accB[2*p+1] += fsig(fb.y * scF[2*p+1] + shF[2*p+1]) * fsp(cb.y * scC[2*p+1] + shC[2*p+1]);
        }
    }
    {
        float* dst = &g_accum[(size_t)curA * AF + c8 * 8];
#pragma unroll
        for (int q = 0; q < 8; q++) atomicAdd(dst + q, accA[q]);
    }
    {
        float* dst = &g_accum[(size_t)curB * AF + c8 * 8];
#pragma unroll
        for (int q = 0; q < 8; q++) atomicAdd(dst + q, accB[q]);
    }
}

// ---------------- BN2 stats ----------------
__global__ __launch_bounds__(256, 4)
void k_bn2stats() {
    __shared__ float rs[256], rq[256];
    int tid = threadIdx.x;
    int c = tid & 63;
    int j = tid >> 6;
    int a0 = blockIdx.x * 2048;
    float s = 0.f, q = 0.f;
    for (int a = a0 + j; a < a0 + 2048; a += 4) {
        if (a < NA) {
            float v = g_accum[(size_t)a * AF + c];
            s += v; q += v * v;
        }
    }
    rs[tid] = s; rq[tid] = q;
    __syncthreads();
    if (tid < 64) {
        float ts = rs[tid] + rs[tid + 64] + rs[tid + 128] + rs[tid + 192];
        float tq = rq[tid] + rq[tid + 64] + rq[tid + 128] + rq[tid + 192];
        atomicAdd(&g_stats2[tid],      ts);
        atomicAdd(&g_stats2[64 + tid], tq);
    }
}

// ---------------- BN2 prep (+ zero stats for next layer) ----------------
__global__ void k_bnprep2(const float* __restrict__ bn2g,
                          const float* __restrict__ bn2b, int layer) {
    int c = threadIdx.x;
    if (c < AF) {
        float invN = 1.f / (float)NA;
        float m = g_stats2[c] * invN;
        float v = g_stats2[AF + c] * invN - m * m;
        float sc = bn2g[layer * AF + c] * rsqrtf(v + EPSF);
        g_scale2[c] = sc;
        g_shift2[c] = bn2b[layer * AF + c] - m * sc;
        g_stats2[c] = 0.f;
        g_stats2[AF + c] = 0.f;
    }
}

// ---------------- residual update (float4; zeroes accum for next layer) ----------------
__global__ void k_update() {
    int i = blockIdx.x * blockDim.x + threadIdx.x;
    if (i < NA * AF / 4) {
        int c = (i * 4) & 63;
        float4 xv = ((const float4*)g_x)[i];
        float4 av = ((const float4*)g_accum)[i];
        float4 sc = *(const float4*)&g_scale2[c];
        float4 sh = *(const float4*)&g_shift2[c];
        float v0 = fsp(xv.x + av.x * sc.x + sh.x);
        float v1 = fsp(xv.y + av.y * sc.y + sh.y);
        float v2 = fsp(xv.z + av.z * sc.z + sh.z);
        float v3 = fsp(xv.w + av.w * sc.w + sh.w);
        ((float4*)g_x)[i] = make_float4(v0, v1, v2, v3);
        ((float4*)g_accum)[i] = make_float4(0.f, 0.f, 0.f, 0.f);
        __half2 h01 = __floats2half2_rn(v0, v1);
        __half2 h23 = __floats2half2_rn(v2, v3);
        uint2 u; u.x = *(unsigned*)&h01; u.y = *(unsigned*)&h23;
        ((uint2*)g_xh)[i] = u;
    }
}

// ---------------- pooling ----------------
__global__ void k_poolclear() {
    int i = blockIdx.x * blockDim.x + threadIdx.x;
    if (i < NC0 * AF) g_pool[i] = 0.f;
    if (i < NC0)      g_cnt[i]  = 0.f;
}

__global__ __launch_bounds__(256, 4)
void k_pool(const int* __restrict__ crysi) {
    int tid = threadIdx.x;
    int c = tid & 63;
    int j = tid >> 6;
    int a0 = blockIdx.x * 256 + j * 64;
    if (a0 >= NA) return;
    float accv = 0.f, accn = 0.f;
    int cur = crysi[a0];
    for (int t = 0; t < 64; t++) {
        int a = a0 + t;
        if (a >= NA) break;
        int idx = crysi[a];
        if (idx != cur) {
            atomicAdd(&g_pool[(size_t)cur * AF + c], accv);
            if (c == 0) atomicAdd(&g_cnt[cur], accn);
            accv = 0.f; accn = 0.f; cur = idx;
        }
        accv += g_x[(size_t)a * AF + c];
        accn += 1.f;
    }
    atomicAdd(&g_pool[(size_t)cur * AF + c], accv);
    if (c == 0) atomicAdd(&g_cnt[cur], accn);
}

// ---------------- head MLP ----------------
__global__ __launch_bounds__(128, 8)
void k_head(const float* __restrict__ W1, const float* __restrict__ b1,
            const float* __restrict__ W2, const float* __restrict__ b2,
            float* __restrict__ out) {
    __shared__ float sc[64];
    __shared__ float red[128];
    int cr = blockIdx.x;
    int tid = threadIdx.x;
    if (tid < 64) {
        float n = g_cnt[cr];
        float crys = g_pool[(size_t)cr * AF + tid] / fmaxf(n, 1.f);
        sc[tid] = fsp(crys);
    }
    __syncthreads();
    float acc = b1[tid];
#pragma unroll 8
    for (int k = 0; k < 64; k++) acc += sc[k] * W1[k * HF + tid];
    float h = fsp(acc);
    red[tid] = h * W2[tid];
    __syncthreads();
    for (int s = 64; s > 0; s >>= 1) {
        if (tid < s) red[tid] += red[tid + s];
        __syncthreads();
    }
    if (tid == 0) out[cr] = red[0] + b2[0];
}

// ---------------- launch ----------------
extern "C" void kernel_launch(void* const* d_in, const int* in_sizes, int n_in,
                              void* d_out, int out_size) {
    const float* atom_fea = (const float*)d_in[0];
    const float* nbr_fea  = (const float*)d_in[1];
    const int*   selfi    = (const int*)d_in[2];
    const int*   nbri     = (const int*)d_in[3];
    const int*   crysi    = (const int*)d_in[4];
    const float* emb_W    = (const float*)d_in[5];
    const float* emb_b    = (const float*)d_in[6];
    const float* conv_W   = (const float*)d_in[7];
    // d_in[8] conv_b cancels through BN1 — unused
    const float* bn1_g    = (const float*)d_in[9];
    const float* bn1_b    = (const float*)d_in[10];
    const float* bn2_g    = (const float*)d_in[11];
    const float* bn2_b    = (const float*)d_in[12];
    const float* fc1_W    = (const float*)d_in[13];
    const float* fc1_b    = (const float*)d_in[14];
    const float* out_W    = (const float*)d_in[15];
    const float* out_b    = (const float*)d_in[16];
    float* out = (float*)d_out;

    int eb = NE / 128;                       // 9375
    int mb = NE / EPB;                       // 1875

    // Launch order: k_edgegemm is the 4th launch (ncu capture slot).
    k_wprep<<<(3 * NKC * 16 * 32 + 255) / 256, 256>>>(conv_W);                 // 1
    k_nbrprep<<<(int)(((size_t)NE * 6 + 255) / 256), 256>>>(nbr_fea);          // 2 (+zero init)
    k_embed<<<(NA + 63) / 64, 256>>>(atom_fea, emb_W, emb_b);                  // 3

    for (int layer = 0; layer < 3; layer++) {
        k_edgegemm<<<eb, 256>>>(selfi, nbri, layer);                           // 4 on layer 0
        k_bnprep1<<<1, 128>>>(bn1_g, bn1_b, layer);
        k_message<<<mb, 256>>>(selfi);
        k_bn2stats<<<(NA + 2047) / 2048, 256>>>();
        k_bnprep2<<<1, 64>>>(bn2_g, bn2_b, layer);
        k_update<<<(NA * AF / 4 + 255) / 256, 256>>>();
    }
    k_poolclear<<<(NC0 * AF + 255) / 256, 256>>>();
    k_pool<<<(NA + 255) / 256, 256>>>(crysi);
    k_head<<<NC0, 128>>>(fc1_W, fc1_b, out_W, out_b, out);
}

// round 16
// speedup vs baseline: 1.0711x; 1.0711x over previous
#include <cuda_runtime.h>
#include <cuda_fp16.h>

#define NA   100000
#define NE   1200000
#define NC0  3125
#define ORIG 92
#define NBRF 41
#define AF   64
#define HF   128
#define COUT 128
#define KTOT 169
#define NKC  11       // 11*16 = 176 padded K
#define KPAD2 184     // smem A row stride in halves (368 B)
#define YRS   136     // smem Y staging row stride in halves (272 B = 17*16)
#define EPB  480      // edges per k_message block (NE/480 = 2500)
#define EPSF 1e-5f

// ---------------- device scratch (no allocation) ----------------
__device__ __align__(16) __half   g_xh[NA * AF];
__device__ __align__(16) float    g_x[NA * AF];
__device__ __align__(16) __half   g_y[(size_t)NE * COUT];
__device__ __align__(16) __half   g_nbrh[(size_t)NE * 48];
__device__ __align__(16) float    g_accum[NA * AF];
__device__ float    g_stats1[2 * COUT];
__device__ __align__(16) float    g_scale1[COUT];
__device__ __align__(16) float    g_shift1[COUT];
__device__ float    g_stats2[2 * AF];
__device__ __align__(16) float    g_scale2[AF];
__device__ __align__(16) float    g_shift2[AF];
__device__ __align__(16) unsigned g_wfrag[3 * NKC * 16 * 32 * 2];
__device__ float    g_pool[NC0 * AF];
__device__ float    g_cnt[NC0];

// fast math (MUFU-based)
__device__ __forceinline__ float fsp(float x) {
    return fmaxf(x, 0.f) + __logf(1.f + __expf(-fabsf(x)));
}
// sigmoid via tanh.approx: 1 MUFU instead of 2 (register-neutral)
__device__ __forceinline__ float fsig(float x) {
    float t;
    asm("tanh.approx.f32 %0, %1;" : "=f"(t) : "f"(0.5f * x));
    return fmaf(0.5f, t, 0.5f);
}

__device__ __forceinline__ void ldsm_x4(unsigned &r0, unsigned &r1,
                                        unsigned &r2, unsigned &r3,
                                        unsigned addr) {
    asm volatile("ldmatrix.sync.aligned.m8n8.x4.shared.b16 {%0,%1,%2,%3}, [%4];\n"
                 : "=r"(r0), "=r"(r1), "=r"(r2), "=r"(r3) : "r"(addr));
}
__device__ __forceinline__ void stsm_x4(unsigned addr, unsigned r0, unsigned r1,
                                        unsigned r2, unsigned r3) {
    asm volatile("stmatrix.sync.aligned.m8n8.x4.shared.b16 [%0], {%1,%2,%3,%4};\n"
                 :: "r"(addr), "r"(r0), "r"(r1), "r"(r2), "r"(r3));
}
__device__ __forceinline__ void cp16(unsigned sdst, const void* gsrc) {
    asm volatile("cp.async.cg.shared.global [%0], [%1], 16;\n"
                 :: "r"(sdst), "l"(gsrc));
}

// Y staging swizzle: 16B chunk index XOR low row bits (conflict-free copy-out)
__device__ __forceinline__ unsigned ybyte(int row, int chunk) {
    return (unsigned)(row * (YRS * 2) + ((chunk ^ (row & 7)) << 4));
}

// ---------------- nbr_fea pad+convert (+ global zero-init fused) ----------------
__global__ void k_nbrprep(const float* __restrict__ nbr) {
    size_t t = (size_t)blockIdx.x * blockDim.x + threadIdx.x;
    if (t < (size_t)NA * AF / 4)
        ((float4*)g_accum)[t] = make_float4(0.f, 0.f, 0.f, 0.f);
    if (blockIdx.x == 0) {
        if (threadIdx.x < 2 * COUT) g_stats1[threadIdx.x] = 0.f;
        if (threadIdx.x < 2 * AF)   g_stats2[threadIdx.x] = 0.f;
    }
    if (t >= (size_t)NE * 6) return;       // 6 chunks of 8 halves per edge
    int chunk = (int)(t % 6);
    size_t e = t / 6;
    int c0 = chunk * 8;
    __half h[8];
#pragma unroll
    for (int q = 0; q < 8; q++) {
        int c = c0 + q;
        h[q] = __float2half(c < NBRF ? nbr[e * NBRF + c] : 0.f);
    }
    *(uint4*)&g_nbrh[e * 48 + c0] = *(uint4*)h;
}

// ---------------- B-fragment prep ----------------
__global__ void k_wprep(const float* __restrict__ convW) {
    int i = blockIdx.x * blockDim.x + threadIdx.x;
    int total = 3 * NKC * 16 * 32;
    if (i >= total) return;
    int lane = i & 31;
    int t = i >> 5;
    int nn = t & 15; t >>= 4;
    int kk = t % NKC;
    int l  = t / NKC;
    int n  = nn * 8 + (lane >> 2);
    int kbase = kk * 16 + (lane & 3) * 2;
#pragma unroll
    for (int rgp = 0; rgp < 2; rgp++) {
        int k = kbase + rgp * 8;
        float v0 = (k     < KTOT) ? convW[((size_t)l * KTOT + k)     * COUT + n] : 0.f;
        float v1 = (k + 1 < KTOT) ? convW[((size_t)l * KTOT + k + 1) * COUT + n] : 0.f;
        __half2 h = __floats2half2_rn(v0, v1);
        g_wfrag[(size_t)i * 2 + rgp] = *(unsigned*)&h;
    }
}

// ---------------- embedding ----------------
__global__ __launch_bounds__(256, 2)
void k_embed(const float* __restrict__ af, const float* __restrict__ W,
             const float* __restrict__ b) {
    __shared__ float sW[ORIG * AF];
    __shared__ float sAt[64 * 93];
    int tid = threadIdx.x;
    int a0  = blockIdx.x * 64;
    for (int i = tid; i < ORIG * AF; i += 256) sW[i] = W[i];
    for (int i = tid; i < 64 * ORIG; i += 256) {
        int rr = i / ORIG, kk = i % ORIG;
        int a = a0 + rr;
        sAt[rr * 93 + kk] = (a < NA) ? af[(size_t)a * ORIG + kk] : 0.f;
    }
    __syncthreads();
    int og = (tid & 15) * 4;
    int ag = (tid >> 4) * 4;
    float acc[4][4];
#pragma unroll
    for (int ii = 0; ii < 4; ii++)
#pragma unroll
        for (int j = 0; j < 4; j++) acc[ii][j] = 0.f;
    for (int k = 0; k < ORIG; k++) {
        float wv[4], av[4];
#pragma unroll
        for (int j = 0; j < 4; j++) wv[j] = sW[k * AF + og + j];
#pragma unroll
        for (int ii = 0; ii < 4; ii++) av[ii] = sAt[(ag + ii) * 93 + k];
#pragma unroll
        for (int ii = 0; ii < 4; ii++)
#pragma unroll
            for (int j = 0; j < 4; j++) acc[ii][j] += av[ii] * wv[j];
    }
#pragma unroll
    for (int ii = 0; ii < 4; ii++) {
        int a = a0 + ag + ii;
        if (a < NA) {
#pragma unroll
            for (int j = 0; j < 4; j++) {
                float v = acc[ii][j] + b[og + j];
                g_x[(size_t)a * AF + og + j]  = v;
                g_xh[(size_t)a * AF + og + j] = __float2half(v);
            }
        }
    }
}

// ---------------- edge GEMM + BN1 stats (R8 form, byte-identical) ----------------
__global__ __launch_bounds__(256, 2)
void k_edgegemm(const int* __restrict__ selfi,
                const int* __restrict__ nbri,
                int layer) {
    __shared__ __align__(16) __half sA[128][KPAD2];   // 47104 B (reused as sY)
    __shared__ float sSum[COUT];
    __shared__ float sSq[COUT];
    int tid = threadIdx.x;
    int e0  = blockIdx.x * 128;
    if (tid < COUT) { sSum[tid] = 0.f; sSq[tid] = 0.f; }

    unsigned abase = (unsigned)__cvta_generic_to_shared(&sA[0][0]);

    // gather [x_self | x_nbr | nbr] via cp.async: 2 threads per edge
    {
        int el = tid >> 1;
        int p  = tid & 1;
        int e  = e0 + el;
        int src = p ? nbri[e] : selfi[e];
        const uint4* xr = (const uint4*)(g_xh + (size_t)src * AF);
        unsigned drow = abase + (unsigned)(el * KPAD2 * 2);
        unsigned dx   = drow + (unsigned)(p * 128);
#pragma unroll
        for (int q = 0; q < 8; q++) cp16(dx + q * 16u, xr + q);
        const uint4* nr = (const uint4*)(g_nbrh + (size_t)e * 48);
        unsigned dn = drow + 256u + (unsigned)(p * 48);
#pragma unroll
        for (int q = 0; q < 3; q++) cp16(dn + q * 16u, nr + p * 3 + q);
    }
    asm volatile("cp.async.commit_group;\n");
    asm volatile("cp.async.wait_group 0;\n");
    __syncthreads();

    int lane = tid & 31;
    int warp = tid >> 5;
    int mrb = (warp & 3) * 32;
    int nh  = warp >> 2;
    int ncb = nh * 64;

    unsigned aaddr0 = abase + (unsigned)(((mrb + (lane & 15)) * KPAD2 + ((lane >> 4) * 8)) * 2);
    unsigned aaddr1 = aaddr0 + 16u * KPAD2 * 2u;

    const uint2* __restrict__ wf = (const uint2*)g_wfrag;
    size_t wbase = (((size_t)layer * NKC) * 16 + nh * 8) * 32 + lane;

    float acc[2][8][4];
#pragma unroll
    for (int mi = 0; mi < 2; mi++)
#pragma unroll
        for (int nn = 0; nn < 8; nn++)
#pragma unroll
            for (int r = 0; r < 4; r++) acc[mi][nn][r] = 0.f;

#pragma unroll
    for (int kk = 0; kk < NKC; kk++) {
        unsigned a[2][4];
        ldsm_x4(a[0][0], a[0][1], a[0][2], a[0][3], aaddr0 + kk * 32u);
        ldsm_x4(a[1][0], a[1][1], a[1][2], a[1][3], aaddr1 + kk * 32u);
        uint2 b[8];
#pragma unroll
        for (int nn = 0; nn < 8; nn++)
            b[nn] = wf[wbase + (size_t)kk * 16 * 32 + (size_t)nn * 32];
#pragma unroll
        for (int nn = 0; nn < 8; nn++) {
#pragma unroll
            for (int mi = 0; mi < 2; mi++) {
                asm volatile(
                    "mma.sync.aligned.m16n8k16.row.col.f32.f16.f16.f32 "
                    "{%0,%1,%2,%3}, {%4,%5,%6,%7}, {%8,%9}, {%0,%1,%2,%3};\n"
                    : "+f"(acc[mi][nn][0]), "+f"(acc[mi][nn][1]),
                      "+f"(acc[mi][nn][2]), "+f"(acc[mi][nn][3])
                    : "r"(a[mi][0]), "r"(a[mi][1]), "r"(a[mi][2]), "r"(a[mi][3]),
                      "r"(b[nn].x), "r"(b[nn].y));
            }
        }
    }

    // per-column sum/sumsq from registers
    float cs[8][2], cq[8][2];
#pragma unroll
    for (int nn = 0; nn < 8; nn++)
#pragma unroll
        for (int j = 0; j < 2; j++) { cs[nn][j] = 0.f; cq[nn][j] = 0.f; }
#pragma unroll
    for (int mi = 0; mi < 2; mi++)
#pragma unroll
        for (int nn = 0; nn < 8; nn++) {
            float d0 = acc[mi][nn][0], d1 = acc[mi][nn][1];
            float d2 = acc[mi][nn][2], d3 = acc[mi][nn][3];
            cs[nn][0] += d0 + d2; cq[nn][0] += d0 * d0 + d2 * d2;
            cs[nn][1] += d1 + d3; cq[nn][1] += d1 * d1 + d3 * d3;
        }
#pragma unroll
    for (int nn = 0; nn < 8; nn++)
#pragma unroll
        for (int j = 0; j < 2; j++) {
#pragma unroll
            for (int m = 4; m < 32; m <<= 1) {
                cs[nn][j] += __shfl_xor_sync(0xffffffffu, cs[nn][j], m);
                cq[nn][j] += __shfl_xor_sync(0xffffffffu, cq[nn][j], m);
            }
        }

    // stage y via stmatrix (reuse sA), then coalesced copy-out
    __syncthreads();
    {
        int tile = lane >> 3;
        int rrow = lane & 7;
        int rowb = mrb + ((tile & 1) ? 8 : 0) + rrow;
        int cchk = (ncb >> 3) + ((tile >> 1) ? 1 : 0);
#pragma unroll
        for (int mi = 0; mi < 2; mi++) {
            int row = rowb + mi * 16;
#pragma unroll
            for (int np = 0; np < 4; np++) {
                int nn = np * 2;
                __half2 h0  = __floats2half2_rn(acc[mi][nn][0],     acc[mi][nn][1]);
                __half2 h1  = __floats2half2_rn(acc[mi][nn][2],     acc[mi][nn][3]);
                __half2 h2v = __floats2half2_rn(acc[mi][nn + 1][0], acc[mi][nn + 1][1]);
                __half2 h3  = __floats2half2_rn(acc[mi][nn + 1][2], acc[mi][nn + 1][3]);
                stsm_x4(abase + ybyte(row, cchk + nn),
                        *(unsigned*)&h0, *(unsigned*)&h1,
                        *(unsigned*)&h2v, *(unsigned*)&h3);
            }
        }
    }
    __syncthreads();
    {
#pragma unroll
        for (int q = 0; q < 4; q++) {
            int idx = tid + q * 256;
            int row = idx >> 3;
            int j   = idx & 7;
            uint4 v0 = *(const uint4*)((const char*)&sA[0][0] + ybyte(row, 2 * j));
            *(uint4*)&g_y[(size_t)(e0 + row) * COUT + (2 * j) * 8] = v0;
            uint4 v1 = *(const uint4*)((const char*)&sA[0][0] + ybyte(row, 2 * j + 1));
            *(uint4*)&g_y[(size_t)(e0 + row) * COUT + (2 * j + 1) * 8] = v1;
        }
    }

    if (lane < 4) {
#pragma unroll
        for (int nn = 0; nn < 8; nn++)
#pragma unroll
            for (int j = 0; j < 2; j++) {
                int c = ncb + nn * 8 + lane * 2 + j;
                atomicAdd(&sSum[c], cs[nn][j]);
                atomicAdd(&sSq[c],  cq[nn][j]);
            }
    }
    __syncthreads();
    if (tid < COUT) {
        atomicAdd(&g_stats1[tid],        sSum[tid]);
        atomicAdd(&g_stats1[COUT + tid], sSq[tid]);
    }
}

// ---------------- BN1 prep (+ zero stats for next layer) ----------------
__global__ void k_bnprep1(const float* __restrict__ bn1g,
                          const float* __restrict__ bn1b, int layer) {
    int c = threadIdx.x;
    if (c < COUT) {
        float invE = 1.f / (float)NE;
        float m = g_stats1[c] * invE;
        float v = g_stats1[COUT + c] * invE - m * m;
        float sc = bn1g[layer * COUT + c] * rsqrtf(v + EPSF);
        g_scale1[c] = sc;
        g_shift1[c] = bn1b[layer * COUT + c] - m * sc;
        g_stats1[c] = 0.f;
        g_stats1[COUT + c] = 0.f;
    }
}

// ---------------- message + segment sum (R8 form; tanh sigmoid only change) ----------------
__global__ __launch_bounds__(256, 4)
void k_message(const int* __restrict__ selfi) {
    __shared__ int sIdx[EPB];
    int tid = threadIdx.x;
    int e0  = blockIdx.x * EPB;
    for (int i = tid; i < EPB; i += 256) sIdx[i] = selfi[e0 + i];
    __syncthreads();
    int c8 = tid & 7;
    int j  = tid >> 3;
    float scF[8], shF[8], scC[8], shC[8];
#pragma unroll
    for (int q = 0; q < 8; q++) {
        scF[q] = g_scale1[c8 * 8 + q];      shF[q] = g_shift1[c8 * 8 + q];
        scC[q] = g_scale1[64 + c8 * 8 + q]; shC[q] = g_shift1[64 + c8 * 8 + q];
    }
    int base = j * 15;
    float acc8[8];
#pragma unroll
    for (int q = 0; q < 8; q++) acc8[q] = 0.f;
    int cur = sIdx[base];
#pragma unroll 3
    for (int t = 0; t < 15; t++) {
        int el = base + t;
        size_t e = (size_t)(e0 + el);
        uint4 fv = *(const uint4*)&g_y[e * COUT + c8 * 8];
        uint4 cv = *(const uint4*)&g_y[e * COUT + 64 + c8 * 8];
        const __half2* fh = (const __half2*)&fv;
        const __half2* ch = (const __half2*)&cv;
        int idx = sIdx[el];
        if (idx != cur) {
            float* dst = &g_accum[(size_t)cur * AF + c8 * 8];
#pragma unroll
            for (int q = 0; q < 8; q++) { atomicAdd(dst + q, acc8[q]); acc8[q] = 0.f; }
            cur = idx;
        }
#pragma unroll
        for (int p = 0; p < 4; p++) {
            float2 f2 = __half22float2(fh[p]);
            float2 g2 = __half22float2(ch[p]);
            float f0 = f2.x * scF[2 * p]     + shF[2 * p];
            float f1 = f2.y * scF[2 * p + 1] + shF[2 * p + 1];
            float c0 = g2.x * scC[2 * p]     + shC[2 * p];
            float c1 = g2.y * scC[2 * p + 1] + shC[2 * p + 1];
            acc8[2 * p]     += fsig(f0) * fsp(c0);
            acc8[2 * p + 1] += fsig(f1) * fsp(c1);
        }
    }
    float* dst = &g_accum[(size_t)cur * AF + c8 * 8];
#pragma unroll
    for (int q = 0; q < 8; q++) atomicAdd(dst + q, acc8[q]);
}

// ---------------- BN2 stats ----------------
__global__ __launch_bounds__(256, 4)
void k_bn2stats() {
    __shared__ float rs[256], rq[256];
    int tid = threadIdx.x;
    int c = tid & 63;
    int j = tid >> 6;
    int a0 = blockIdx.x * 2048;
    float s = 0.f, q = 0.f;
    for (int a = a0 + j; a < a0 + 2048; a += 4) {
        if (a < NA) {
            float v = g_accum[(size_t)a * AF + c];
            s += v; q += v * v;
        }
    }
    rs[tid] = s; rq[tid] = q;
    __syncthreads();
    if (tid < 64) {
        float ts = rs[tid] + rs[tid + 64] + rs[tid + 128] + rs[tid + 192];
        float tq = rq[tid] + rq[tid + 64] + rq[tid + 128] + rq[tid + 192];
        atomicAdd(&g_stats2[tid],      ts);
        atomicAdd(&g_stats2[64 + tid], tq);
    }
}

// ---------------- BN2 prep (+ zero stats for next layer) ----------------
__global__ void k_bnprep2(const float* __restrict__ bn2g,
                          const float* __restrict__ bn2b, int layer) {
    int c = threadIdx.x;
    if (c < AF) {
        float invN = 1.f / (float)NA;
        float m = g_stats2[c] * invN;
        float v = g_stats2[AF + c] * invN - m * m;
        float sc = bn2g[layer * AF + c] * rsqrtf(v + EPSF);
        g_scale2[c] = sc;
        g_shift2[c] = bn2b[layer * AF + c] - m * sc;
        g_stats2[c] = 0.f;
        g_stats2[AF + c] = 0.f;
    }
}

// ---------------- residual update (float4; zeroes accum for next layer) ----------------
__global__ void k_update() {
    int i = blockIdx.x * blockDim.x + threadIdx.x;
    if (i < NA * AF / 4) {
        int c = (i * 4) & 63;
        float4 xv = ((const float4*)g_x)[i];
        float4 av = ((const float4*)g_accum)[i];
        float4 sc = *(const float4*)&g_scale2[c];
        float4 sh = *(const float4*)&g_shift2[c];
        float v0 = fsp(xv.x + av.x * sc.x + sh.x);
        float v1 = fsp(xv.y + av.y * sc.y + sh.y);
        float v2 = fsp(xv.z + av.z * sc.z + sh.z);
        float v3 = fsp(xv.w + av.w * sc.w + sh.w);
        ((float4*)g_x)[i] = make_float4(v0, v1, v2, v3);
        ((float4*)g_accum)[i] = make_float4(0.f, 0.f, 0.f, 0.f);
        __half2 h01 = __floats2half2_rn(v0, v1);
        __half2 h23 = __floats2half2_rn(v2, v3);
        uint2 u; u.x = *(unsigned*)&h01; u.y = *(unsigned*)&h23;
        ((uint2*)g_xh)[i] = u;
    }
}

// ---------------- pooling ----------------
__global__ void k_poolclear() {
    int i = blockIdx.x * blockDim.x + threadIdx.x;
    if (i < NC0 * AF) g_pool[i] = 0.f;
    if (i < NC0)      g_cnt[i]  = 0.f;
}

__global__ __launch_bounds__(256, 4)
void k_pool(const int* __restrict__ crysi) {
    int tid = threadIdx.x;
    int c = tid & 63;
    int j = tid >> 6;
    int a0 = blockIdx.x * 256 + j * 64;
    if (a0 >= NA) return;
    float accv = 0.f, accn = 0.f;
    int cur = crysi[a0];
    for (int t = 0; t < 64; t++) {
        int a = a0 + t;
        if (a >= NA) break;
        int idx = crysi[a];
        if (idx != cur) {
            atomicAdd(&g_pool[(size_t)cur * AF + c], accv);
            if (c == 0) atomicAdd(&g_cnt[cur], accn);
            accv = 0.f; accn = 0.f; cur = idx;
        }
        accv += g_x[(size_t)a * AF + c];
        accn += 1.f;
    }
    atomicAdd(&g_pool[(size_t)cur * AF + c], accv);
    if (c == 0) atomicAdd(&g_cnt[cur], accn);
}

// ---------------- head MLP ----------------
__global__ __launch_bounds__(128, 8)
void k_head(const float* __restrict__ W1, const float* __restrict__ b1,
            const float* __restrict__ W2, const float* __restrict__ b2,
            float* __restrict__ out) {
    __shared__ float sc[64];
    __shared__ float red[128];
    int cr = blockIdx.x;
    int tid = threadIdx.x;
    if (tid < 64) {
        float n = g_cnt[cr];
        float crys = g_pool[(size_t)cr * AF + tid] / fmaxf(n, 1.f);
        sc[tid] = fsp(crys);
    }
    __syncthreads();
    float acc = b1[tid];
#pragma unroll 8
    for (int k = 0; k < 64; k++) acc += sc[k] * W1[k * HF + tid];
    float h = fsp(acc);
    red[tid] = h * W2[tid];
    __syncthreads();
    for (int s = 64; s > 0; s >>= 1) {
        if (tid < s) red[tid] += red[tid + s];
        __syncthreads();
    }
    if (tid == 0) out[cr] = red[0] + b2[0];
}

// ---------------- launch ----------------
extern "C" void kernel_launch(void* const* d_in, const int* in_sizes, int n_in,
                              void* d_out, int out_size) {
    const float* atom_fea = (const float*)d_in[0];
    const float* nbr_fea  = (const float*)d_in[1];
    const int*   selfi    = (const int*)d_in[2];
    const int*   nbri     = (const int*)d_in[3];
    const int*   crysi    = (const int*)d_in[4];
    const float* emb_W    = (const float*)d_in[5];
    const float* emb_b    = (const float*)d_in[6];
    const float* conv_W   = (const float*)d_in[7];
    // d_in[8] conv_b cancels through BN1 — unused
    const float* bn1_g    = (const float*)d_in[9];
    const float* bn1_b    = (const float*)d_in[10];
    const float* bn2_g    = (const float*)d_in[11];
    const float* bn2_b    = (const float*)d_in[12];
    const float* fc1_W    = (const float*)d_in[13];
    const float* fc1_b    = (const float*)d_in[14];
    const float* out_W    = (const float*)d_in[15];
    const float* out_b    = (const float*)d_in[16];
    float* out = (float*)d_out;

    int eb = NE / 128;                       // 9375
    int mb = NE / EPB;                       // 2500

    // Launch order: k_edgegemm is the 4th launch (ncu capture slot).
    k_wprep<<<(3 * NKC * 16 * 32 + 255) / 256, 256>>>(conv_W);                 // 1
    k_nbrprep<<<(int)(((size_t)NE * 6 + 255) / 256), 256>>>(nbr_fea);          // 2 (+zero init)
    k_embed<<<(NA + 63) / 64, 256>>>(atom_fea, emb_W, emb_b);                  // 3

    for (int layer = 0; layer < 3; layer++) {
        k_edgegemm<<<eb, 256>>>(selfi, nbri, layer);                           // 4 on layer 0
        k_bnprep1<<<1, 128>>>(bn1_g, bn1_b, layer);
        k_message<<<mb, 256>>>(selfi);
        k_bn2stats<<<(NA + 2047) / 2048, 256>>>();
        k_bnprep2<<<1, 64>>>(bn2_g, bn2_b, layer);
        k_update<<<(NA * AF / 4 + 255) / 256, 256>>>();
    }
    k_poolclear<<<(NC0 * AF + 255) / 256, 256>>>();
    k_pool<<<(NA + 255) / 256, 256>>>(crysi);
    k_head<<<NC0, 128>>>(fc1_W, fc1_b, out_W, out_b, out);
}

// round 17
// speedup vs baseline: 1.0934x; 1.0209x over previous
#include <cuda_runtime.h>
#include <cuda_fp16.h>

#define NA   100000
#define NE   1200000
#define NC0  3125
#define ORIG 92
#define NBRF 41
#define AF   64
#define HF   128
#define COUT 128
#define KTOT 169
#define NKC  11       // 11*16 = 176 padded K
#define KPAD2 184     // smem A row stride in halves (368 B)
#define YRS   136     // smem Y staging row stride in halves (272 B = 17*16)
#define EPB  640      // edges per k_message block (NE/640 = 1875)
#define EPSF 1e-5f

// ---------------- device scratch (no allocation) ----------------
__device__ __align__(16) __half   g_xh[NA * AF];
__device__ __align__(16) float    g_x[NA * AF];
__device__ __align__(16) __half   g_y[(size_t)NE * COUT];
__device__ __align__(16) __half   g_nbrh[(size_t)NE * 48];
__device__ __align__(16) float    g_accum[NA * AF];
__device__ float    g_stats1[2 * COUT];
__device__ __align__(16) float    g_scale1[COUT];
__device__ __align__(16) float    g_shift1[COUT];
__device__ float    g_stats2[2 * AF];
__device__ __align__(16) float    g_scale2[AF];
__device__ __align__(16) float    g_shift2[AF];
__device__ __align__(16) unsigned g_wfrag[3 * NKC * 16 * 32 * 2];
__device__ float    g_pool[NC0 * AF];
__device__ float    g_cnt[NC0];

// fast math (MUFU-based)
__device__ __forceinline__ float fsp(float x) {
    return fmaxf(x, 0.f) + __logf(1.f + __expf(-fabsf(x)));
}
// sigmoid via tanh.approx: 1 MUFU (register-neutral)
__device__ __forceinline__ float fsig(float x) {
    float t;
    asm("tanh.approx.f32 %0, %1;" : "=f"(t) : "f"(0.5f * x));
    return fmaf(0.5f, t, 0.5f);
}

__device__ __forceinline__ void ldsm_x4(unsigned &r0, unsigned &r1,
                                        unsigned &r2, unsigned &r3,
                                        unsigned addr) {
    asm volatile("ldmatrix.sync.aligned.m8n8.x4.shared.b16 {%0,%1,%2,%3}, [%4];\n"
                 : "=r"(r0), "=r"(r1), "=r"(r2), "=r"(r3) : "r"(addr));
}
__device__ __forceinline__ void stsm_x4(unsigned addr, unsigned r0, unsigned r1,
                                        unsigned r2, unsigned r3) {
    asm volatile("stmatrix.sync.aligned.m8n8.x4.shared.b16 [%0], {%1,%2,%3,%4};\n"
                 :: "r"(addr), "r"(r0), "r"(r1), "r"(r2), "r"(r3));
}
__device__ __forceinline__ void cp16(unsigned sdst, const void* gsrc) {
    asm volatile("cp.async.cg.shared.global [%0], [%1], 16;\n"
                 :: "r"(sdst), "l"(gsrc));
}

// Y staging swizzle: 16B chunk index XOR low row bits (conflict-free copy-out)
__device__ __forceinline__ unsigned ybyte(int row, int chunk) {
    return (unsigned)(row * (YRS * 2) + ((chunk ^ (row & 7)) << 4));
}

// ---------------- nbr_fea pad+convert (+ global zero-init fused) ----------------
__global__ void k_nbrprep(const float* __restrict__ nbr) {
    size_t t = (size_t)blockIdx.x * blockDim.x + threadIdx.x;
    if (t < (size_t)NA * AF / 4)
        ((float4*)g_accum)[t] = make_float4(0.f, 0.f, 0.f, 0.f);
    if (blockIdx.x == 0) {
        if (threadIdx.x < 2 * COUT) g_stats1[threadIdx.x] = 0.f;
        if (threadIdx.x < 2 * AF)   g_stats2[threadIdx.x] = 0.f;
    }
    if (t >= (size_t)NE * 6) return;       // 6 chunks of 8 halves per edge
    int chunk = (int)(t % 6);
    size_t e = t / 6;
    int c0 = chunk * 8;
    __half h[8];
#pragma unroll
    for (int q = 0; q < 8; q++) {
        int c = c0 + q;
        h[q] = __float2half(c < NBRF ? nbr[e * NBRF + c] : 0.f);
    }
    *(uint4*)&g_nbrh[e * 48 + c0] = *(uint4*)h;
}

// ---------------- B-fragment prep ----------------
__global__ void k_wprep(const float* __restrict__ convW) {
    int i = blockIdx.x * blockDim.x + threadIdx.x;
    int total = 3 * NKC * 16 * 32;
    if (i >= total) return;
    int lane = i & 31;
    int t = i >> 5;
    int nn = t & 15; t >>= 4;
    int kk = t % NKC;
    int l  = t / NKC;
    int n  = nn * 8 + (lane >> 2);
    int kbase = kk * 16 + (lane & 3) * 2;
#pragma unroll
    for (int rgp = 0; rgp < 2; rgp++) {
        int k = kbase + rgp * 8;
        float v0 = (k     < KTOT) ? convW[((size_t)l * KTOT + k)     * COUT + n] : 0.f;
        float v1 = (k + 1 < KTOT) ? convW[((size_t)l * KTOT + k + 1) * COUT + n] : 0.f;
        __half2 h = __floats2half2_rn(v0, v1);
        g_wfrag[(size_t)i * 2 + rgp] = *(unsigned*)&h;
    }
}

// ---------------- embedding ----------------
__global__ __launch_bounds__(256, 2)
void k_embed(const float* __restrict__ af, const float* __restrict__ W,
             const float* __restrict__ b) {
    __shared__ float sW[ORIG * AF];
    __shared__ float sAt[64 * 93];
    int tid = threadIdx.x;
    int a0  = blockIdx.x * 64;
    for (int i = tid; i < ORIG * AF; i += 256) sW[i] = W[i];
    for (int i = tid; i < 64 * ORIG; i += 256) {
        int rr = i / ORIG, kk = i % ORIG;
        int a = a0 + rr;
        sAt[rr * 93 + kk] = (a < NA) ? af[(size_t)a * ORIG + kk] : 0.f;
    }
    __syncthreads();
    int og = (tid & 15) * 4;
    int ag = (tid >> 4) * 4;
    float acc[4][4];
#pragma unroll
    for (int ii = 0; ii < 4; ii++)
#pragma unroll
        for (int j = 0; j < 4; j++) acc[ii][j] = 0.f;
    for (int k = 0; k < ORIG; k++) {
        float wv[4], av[4];
#pragma unroll
        for (int j = 0; j < 4; j++) wv[j] = sW[k * AF + og + j];
#pragma unroll
        for (int ii = 0; ii < 4; ii++) av[ii] = sAt[(ag + ii) * 93 + k];
#pragma unroll
        for (int ii = 0; ii < 4; ii++)
#pragma unroll
            for (int j = 0; j < 4; j++) acc[ii][j] += av[ii] * wv[j];
    }
#pragma unroll
    for (int ii = 0; ii < 4; ii++) {
        int a = a0 + ag + ii;
        if (a < NA) {
#pragma unroll
            for (int j = 0; j < 4; j++) {
                float v = acc[ii][j] + b[og + j];
                g_x[(size_t)a * AF + og + j]  = v;
                g_xh[(size_t)a * AF + og + j] = __float2half(v);
            }
        }
    }
}

// ---------------- edge GEMM + BN1 stats (R8 form, byte-identical) ----------------
__global__ __launch_bounds__(256, 2)
void k_edgegemm(const int* __restrict__ selfi,
                const int* __restrict__ nbri,
                int layer) {
    __shared__ __align__(16) __half sA[128][KPAD2];   // 47104 B (reused as sY)
    __shared__ float sSum[COUT];
    __shared__ float sSq[COUT];
    int tid = threadIdx.x;
    int e0  = blockIdx.x * 128;
    if (tid < COUT) { sSum[tid] = 0.f; sSq[tid] = 0.f; }

    unsigned abase = (unsigned)__cvta_generic_to_shared(&sA[0][0]);

    // gather [x_self | x_nbr | nbr] via cp.async: 2 threads per edge
    {
        int el = tid >> 1;
        int p  = tid & 1;
        int e  = e0 + el;
        int src = p ? nbri[e] : selfi[e];
        const uint4* xr = (const uint4*)(g_xh + (size_t)src * AF);
        unsigned drow = abase + (unsigned)(el * KPAD2 * 2);
        unsigned dx   = drow + (unsigned)(p * 128);
#pragma unroll
        for (int q = 0; q < 8; q++) cp16(dx + q * 16u, xr + q);
        const uint4* nr = (const uint4*)(g_nbrh + (size_t)e * 48);
        unsigned dn = drow + 256u + (unsigned)(p * 48);
#pragma unroll
        for (int q = 0; q < 3; q++) cp16(dn + q * 16u, nr + p * 3 + q);
    }
    asm volatile("cp.async.commit_group;\n");
    asm volatile("cp.async.wait_group 0;\n");
    __syncthreads();

    int lane = tid & 31;
    int warp = tid >> 5;
    int mrb = (warp & 3) * 32;
    int nh  = warp >> 2;
    int ncb = nh * 64;

    unsigned aaddr0 = abase + (unsigned)(((mrb + (lane & 15)) * KPAD2 + ((lane >> 4) * 8)) * 2);
    unsigned aaddr1 = aaddr0 + 16u * KPAD2 * 2u;

    const uint2* __restrict__ wf = (const uint2*)g_wfrag;
    size_t wbase = (((size_t)layer * NKC) * 16 + nh * 8) * 32 + lane;

    float acc[2][8][4];
#pragma unroll
    for (int mi = 0; mi < 2; mi++)
#pragma unroll
        for (int nn = 0; nn < 8; nn++)
#pragma unroll
            for (int r = 0; r < 4; r++) acc[mi][nn][r] = 0.f;

#pragma unroll
    for (int kk = 0; kk < NKC; kk++) {
        unsigned a[2][4];
        ldsm_x4(a[0][0], a[0][1], a[0][2], a[0][3], aaddr0 + kk * 32u);
        ldsm_x4(a[1][0], a[1][1], a[1][2], a[1][3], aaddr1 + kk * 32u);
        uint2 b[8];
#pragma unroll
        for (int nn = 0; nn < 8; nn++)
            b[nn] = wf[wbase + (size_t)kk * 16 * 32 + (size_t)nn * 32];
#pragma unroll
        for (int nn = 0; nn < 8; nn++) {
#pragma unroll
            for (int mi = 0; mi < 2; mi++) {
                asm volatile(
                    "mma.sync.aligned.m16n8k16.row.col.f32.f16.f16.f32 "
                    "{%0,%1,%2,%3}, {%4,%5,%6,%7}, {%8,%9}, {%0,%1,%2,%3};\n"
                    : "+f"(acc[mi][nn][0]), "+f"(acc[mi][nn][1]),
                      "+f"(acc[mi][nn][2]), "+f"(acc[mi][nn][3])
                    : "r"(a[mi][0]), "r"(a[mi][1]), "r"(a[mi][2]), "r"(a[mi][3]),
                      "r"(b[nn].x), "r"(b[nn].y));
            }
        }
    }

    // per-column sum/sumsq from registers
    float cs[8][2], cq[8][2];
#pragma unroll
    for (int nn = 0; nn < 8; nn++)
#pragma unroll
        for (int j = 0; j < 2; j++) { cs[nn][j] = 0.f; cq[nn][j] = 0.f; }
#pragma unroll
    for (int mi = 0; mi < 2; mi++)
#pragma unroll
        for (int nn = 0; nn < 8; nn++) {
            float d0 = acc[mi][nn][0], d1 = acc[mi][nn][1];
            float d2 = acc[mi][nn][2], d3 = acc[mi][nn][3];
            cs[nn][0] += d0 + d2; cq[nn][0] += d0 * d0 + d2 * d2;
            cs[nn][1] += d1 + d3; cq[nn][1] += d1 * d1 + d3 * d3;
        }
#pragma unroll
    for (int nn = 0; nn < 8; nn++)
#pragma unroll
        for (int j = 0; j < 2; j++) {
#pragma unroll
            for (int m = 4; m < 32; m <<= 1) {
                cs[nn][j] += __shfl_xor_sync(0xffffffffu, cs[nn][j], m);
                cq[nn][j] += __shfl_xor_sync(0xffffffffu, cq[nn][j], m);
            }
        }

    // stage y via stmatrix (reuse sA), then coalesced copy-out
    __syncthreads();
    {
        int tile = lane >> 3;
        int rrow = lane & 7;
        int rowb = mrb + ((tile & 1) ? 8 : 0) + rrow;
        int cchk = (ncb >> 3) + ((tile >> 1) ? 1 : 0);
#pragma unroll
        for (int mi = 0; mi < 2; mi++) {
            int row = rowb + mi * 16;
#pragma unroll
            for (int np = 0; np < 4; np++) {
                int nn = np * 2;
                __half2 h0  = __floats2half2_rn(acc[mi][nn][0],     acc[mi][nn][1]);
                __half2 h1  = __floats2half2_rn(acc[mi][nn][2],     acc[mi][nn][3]);
                __half2 h2v = __floats2half2_rn(acc[mi][nn + 1][0], acc[mi][nn + 1][1]);
                __half2 h3  = __floats2half2_rn(acc[mi][nn + 1][2], acc[mi][nn + 1][3]);
                stsm_x4(abase + ybyte(row, cchk + nn),
                        *(unsigned*)&h0, *(unsigned*)&h1,
                        *(unsigned*)&h2v, *(unsigned*)&h3);
            }
        }
    }
    __syncthreads();
    {
#pragma unroll
        for (int q = 0; q < 4; q++) {
            int idx = tid + q * 256;
            int row = idx >> 3;
            int j   = idx & 7;
            uint4 v0 = *(const uint4*)((const char*)&sA[0][0] + ybyte(row, 2 * j));
            *(uint4*)&g_y[(size_t)(e0 + row) * COUT + (2 * j) * 8] = v0;
            uint4 v1 = *(const uint4*)((const char*)&sA[0][0] + ybyte(row, 2 * j + 1));
            *(uint4*)&g_y[(size_t)(e0 + row) * COUT + (2 * j + 1) * 8] = v1;
        }
    }

    if (lane < 4) {
#pragma unroll
        for (int nn = 0; nn < 8; nn++)
#pragma unroll
            for (int j = 0; j < 2; j++) {
                int c = ncb + nn * 8 + lane * 2 + j;
                atomicAdd(&sSum[c], cs[nn][j]);
                atomicAdd(&sSq[c],  cq[nn][j]);
            }
    }
    __syncthreads();
    if (tid < COUT) {
        atomicAdd(&g_stats1[tid],        sSum[tid]);
        atomicAdd(&g_stats1[COUT + tid], sSq[tid]);
    }
}

// ---------------- BN1 prep (+ zero stats for next layer) ----------------
__global__ void k_bnprep1(const float* __restrict__ bn1g,
                          const float* __restrict__ bn1b, int layer) {
    int c = threadIdx.x;
    if (c < COUT) {
        float invE = 1.f / (float)NE;
        float m = g_stats1[c] * invE;
        float v = g_stats1[COUT + c] * invE - m * m;
        float sc = bn1g[layer * COUT + c] * rsqrtf(v + EPSF);
        g_scale1[c] = sc;
        g_shift1[c] = bn1b[layer * COUT + c] - m * sc;
        g_stats1[c] = 0.f;
        g_stats1[COUT + c] = 0.f;
    }
}

// ---------------- message + segment sum: 4 cols/thread, 2 independent streams ----------------
__global__ __launch_bounds__(256, 4)
void k_message(const int* __restrict__ selfi) {
    __shared__ int sIdx[EPB];
    int tid = threadIdx.x;
    int e0  = blockIdx.x * EPB;
    for (int i = tid; i < EPB; i += 256) sIdx[i] = selfi[e0 + i];
    __syncthreads();
    int c4 = tid & 15;         // 4-col group (filt c4*4.. / core 64+c4*4..)
    int j  = tid >> 4;         // 0..15 -> two 20-edge streams at 40j, 40j+20
    float scF[4], shF[4], scC[4], shC[4];
#pragma unroll
    for (int q = 0; q < 4; q++) {
        scF[q] = g_scale1[c4 * 4 + q];      shF[q] = g_shift1[c4 * 4 + q];
        scC[q] = g_scale1[64 + c4 * 4 + q]; shC[q] = g_shift1[64 + c4 * 4 + q];
    }
    int baseA = j * 40;
    int baseB = baseA + 20;
    float accA[4], accB[4];
#pragma unroll
    for (int q = 0; q < 4; q++) { accA[q] = 0.f; accB[q] = 0.f; }
    int curA = sIdx[baseA];
    int curB = sIdx[baseB];
#pragma unroll 4
    for (int t = 0; t < 20; t++) {
        size_t eA = (size_t)(e0 + baseA + t);
        size_t eB = (size_t)(e0 + baseB + t);
        uint2 fvA = *(const uint2*)&g_y[eA * COUT + c4 * 4];
        uint2 cvA = *(const uint2*)&g_y[eA * COUT + 64 + c4 * 4];
        uint2 fvB = *(const uint2*)&g_y[eB * COUT + c4 * 4];
        uint2 cvB = *(const uint2*)&g_y[eB * COUT + 64 + c4 * 4];
        int idxA = sIdx[baseA + t];
        int idxB = sIdx[baseB + t];
        if (idxA != curA) {
            float* dst = &g_accum[(size_t)curA * AF + c4 * 4];
#pragma unroll
            for (int q = 0; q < 4; q++) { atomicAdd(dst + q, accA[q]); accA[q] = 0.f; }
            curA = idxA;
        }
        if (idxB != curB) {
            float* dst = &g_accum[(size_t)curB * AF + c4 * 4];
#pragma unroll
            for (int q = 0; q < 4; q++) { atomicAdd(dst + q, accB[q]); accB[q] = 0.f; }
            curB = idxB;
        }
        const __half2* fhA = (const __half2*)&fvA;
        const __half2* chA = (const __half2*)&cvA;
        const __half2* fhB = (const __half2*)&fvB;
        const __half2* chB = (const __half2*)&cvB;
#pragma unroll
        for (int p = 0; p < 2; p++) {
            float2 fa = __half22float2(fhA[p]);
            float2 ca = __half22float2(chA[p]);
            float2 fb = __half22float2(fhB[p]);
            float2 cb = __half22float2(chB[p]);
            accA[2*p]   += fsig(fa.x * scF[2*p]   + shF[2*p])   * fsp(ca.x * scC[2*p]   + shC[2*p]);
            accA[2*p+1] += fsig(fa.y * scF[2*p+1] + shF[2*p+1]) * fsp(ca.y * scC[2*p+1] + shC[2*p+1]);
            accB[2*p]   += fsig(fb.x * scF[2*p]   + shF[2*p])   * fsp(cb.x * scC[2*p]   + shC[2*p]);
            accB[2*p+1] += fsig(fb.y * scF[2*p+1] + shF[2*p+1]) * fsp(cb.y * scC[2*p+1] + shC[2*p+1]);
        }
    }
    {
        float* dst = &g_accum[(size_t)curA * AF + c4 * 4];
#pragma unroll
        for (int q = 0; q < 4; q++) atomicAdd(dst + q, accA[q]);
    }
    {
        float* dst = &g_accum[(size_t)curB * AF + c4 * 4];
#pragma unroll
        for (int q = 0; q < 4; q++) atomicAdd(dst + q, accB[q]);
    }
}

// ---------------- BN2 stats ----------------
__global__ __launch_bounds__(256, 4)
void k_bn2stats() {
    __shared__ float rs[256], rq[256];
    int tid = threadIdx.x;
    int c = tid & 63;
    int j = tid >> 6;
    int a0 = blockIdx.x * 2048;
    float s = 0.f, q = 0.f;
    for (int a = a0 + j; a < a0 + 2048; a += 4) {
        if (a < NA) {
            float v = g_accum[(size_t)a * AF + c];
            s += v; q += v * v;
        }
    }
    rs[tid] = s; rq[tid] = q;
    __syncthreads();
    if (tid < 64) {
        float ts = rs[tid] + rs[tid + 64] + rs[tid + 128] + rs[tid + 192];
        float tq = rq[tid] + rq[tid + 64] + rq[tid + 128] + rq[tid + 192];
        atomicAdd(&g_stats2[tid],      ts);
        atomicAdd(&g_stats2[64 + tid], tq);
    }
}

// ---------------- BN2 prep (+ zero stats for next layer) ----------------
__global__ void k_bnprep2(const float* __restrict__ bn2g,
                          const float* __restrict__ bn2b, int layer) {
    int c = threadIdx.x;
    if (c < AF) {
        float invN = 1.f / (float)NA;
        float m = g_stats2[c] * invN;
        float v = g_stats2[AF + c] * invN - m * m;
        float sc = bn2g[layer * AF + c] * rsqrtf(v + EPSF);
        g_scale2[c] = sc;
        g_shift2[c] = bn2b[layer * AF + c] - m * sc;
        g_stats2[c] = 0.f;
        g_stats2[AF + c] = 0.f;
    }
}

// ---------------- residual update (float4; zeroes accum for next layer) ----------------
__global__ void k_update() {
    int i = blockIdx.x * blockDim.x + threadIdx.x;
    if (i < NA * AF / 4) {
        int c = (i * 4) & 63;
        float4 xv = ((const float4*)g_x)[i];
        float4 av = ((const float4*)g_accum)[i];
        float4 sc = *(const float4*)&g_scale2[c];
        float4 sh = *(const float4*)&g_shift2[c];
        float v0 = fsp(xv.x + av.x * sc.x + sh.x);
        float v1 = fsp(xv.y + av.y * sc.y + sh.y);
        float v2 = fsp(xv.z + av.z * sc.z + sh.z);
        float v3 = fsp(xv.w + av.w * sc.w + sh.w);
        ((float4*)g_x)[i] = make_float4(v0, v1, v2, v3);
        ((float4*)g_accum)[i] = make_float4(0.f, 0.f, 0.f, 0.f);
        __half2 h01 = __floats2half2_rn(v0, v1);
        __half2 h23 = __floats2half2_rn(v2, v3);
        uint2 u; u.x = *(unsigned*)&h01; u.y = *(unsigned*)&h23;
        ((uint2*)g_xh)[i] = u;
    }
}

// ---------------- pooling ----------------
__global__ void k_poolclear() {
    int i = blockIdx.x * blockDim.x + threadIdx.x;
    if (i < NC0 * AF) g_pool[i] = 0.f;
    if (i < NC0)      g_cnt[i]  = 0.f;
}

__global__ __launch_bounds__(256, 4)
void k_pool(const int* __restrict__ crysi) {
    int tid = threadIdx.x;
    int c = tid & 63;
    int j = tid >> 6;
    int a0 = blockIdx.x * 256 + j * 64;
    if (a0 >= NA) return;
    float accv = 0.f, accn = 0.f;
    int cur = crysi[a0];
    for (int t = 0; t < 64; t++) {
        int a = a0 + t;
        if (a >= NA) break;
        int idx = crysi[a];
        if (idx != cur) {
            atomicAdd(&g_pool[(size_t)cur * AF + c], accv);
            if (c == 0) atomicAdd(&g_cnt[cur], accn);
            accv = 0.f; accn = 0.f; cur = idx;
        }
        accv += g_x[(size_t)a * AF + c];
        accn += 1.f;
    }
    atomicAdd(&g_pool[(size_t)cur * AF + c], accv);
    if (c == 0) atomicAdd(&g_cnt[cur], accn);
}

// ---------------- head MLP ----------------
__global__ __launch_bounds__(128, 8)
void k_head(const float* __restrict__ W1, const float* __restrict__ b1,
            const float* __restrict__ W2, const float* __restrict__ b2,
            float* __restrict__ out) {
    __shared__ float sc[64];
    __shared__ float red[128];
    int cr = blockIdx.x;
    int tid = threadIdx.x;
    if (tid < 64) {
        float n = g_cnt[cr];
        float crys = g_pool[(size_t)cr * AF + tid] / fmaxf(n, 1.f);
        sc[tid] = fsp(crys);
    }
    __syncthreads();
    float acc = b1[tid];
#pragma unroll 8
    for (int k = 0; k < 64; k++) acc += sc[k] * W1[k * HF + tid];
    float h = fsp(acc);
    red[tid] = h * W2[tid];
    __syncthreads();
    for (int s = 64; s > 0; s >>= 1) {
        if (tid < s) red[tid] += red[tid + s];
        __syncthreads();
    }
    if (tid == 0) out[cr] = red[0] + b2[0];
}

// ---------------- launch ----------------
extern "C" void kernel_launch(void* const* d_in, const int* in_sizes, int n_in,
                              void* d_out, int out_size) {
    const float* atom_fea = (const float*)d_in[0];
    const float* nbr_fea  = (const float*)d_in[1];
    const int*   selfi    = (const int*)d_in[2];
    const int*   nbri     = (const int*)d_in[3];
    const int*   crysi    = (const int*)d_in[4];
    const float* emb_W    = (const float*)d_in[5];
    const float* emb_b    = (const float*)d_in[6];
    const float* conv_W   = (const float*)d_in[7];
    // d_in[8] conv_b cancels through BN1 — unused
    const float* bn1_g    = (const float*)d_in[9];
    const float* bn1_b    = (const float*)d_in[10];
    const float* bn2_g    = (const float*)d_in[11];
    const float* bn2_b    = (const float*)d_in[12];
    const float* fc1_W    = (const float*)d_in[13];
    const float* fc1_b    = (const float*)d_in[14];
    const float* out_W    = (const float*)d_in[15];
    const float* out_b    = (const float*)d_in[16];
    float* out = (float*)d_out;

    int eb = NE / 128;                       // 9375
    int mb = NE / EPB;                       // 1875

    // Launch order: k_edgegemm is the 4th launch (ncu capture slot).
    k_wprep<<<(3 * NKC * 16 * 32 + 255) / 256, 256>>>(conv_W);                 // 1
    k_nbrprep<<<(int)(((size_t)NE * 6 + 255) / 256), 256>>>(nbr_fea);          // 2 (+zero init)
    k_embed<<<(NA + 63) / 64, 256>>>(atom_fea, emb_W, emb_b);                  // 3

    for (int layer = 0; layer < 3; layer++) {
        k_edgegemm<<<eb, 256>>>(selfi, nbri, layer);                           // 4 on layer 0
        k_bnprep1<<<1, 128>>>(bn1_g, bn1_b, layer);
        k_message<<<mb, 256>>>(selfi);
        k_bn2stats<<<(NA + 2047) / 2048, 256>>>();
        k_bnprep2<<<1, 64>>>(bn2_g, bn2_b, layer);
        k_update<<<(NA * AF / 4 + 255) / 256, 256>>>();
    }
    k_poolclear<<<(NC0 * AF + 255) / 256, 256>>>();
    k_pool<<<(NA + 255) / 256, 256>>>(crysi);
    k_head<<<NC0, 128>>>(fc1_W, fc1_b, out_W, out_b, out);
}